// round 1
// baseline (speedup 1.0000x reference)
#include <cuda_runtime.h>
#include <math.h>

#define Bb   16
#define Cc   256
#define NN   9216      // H*W
#define GG   8
#define MDm  64
#define NHh  4
#define HDd  16
#define MKQV 192       // stacked k,v,q output rows

// ---------------- scratch (device globals: no allocs allowed) ----------------
__device__ float g_chansum[Bb*Cc];
__device__ float g_chansq [Bb*Cc];
__device__ float g_Wfold  [Bb*MKQV*Cc];          // per-batch alpha-folded stacked weights
__device__ float g_pbias  [Bb*MKQV];             // per-(b,o) beta-projection bias
__device__ float g_gate   [Bb];
__device__ float g_kqv    [(size_t)Bb*MKQV*NN];  // phi_k rows 0..63, v 64..127, phi_q 128..191
__device__ float g_M      [Bb*NHh*HDd*HDd];
__device__ float g_Z      [Bb*NHh*HDd];

// ---------------- K0: per-(b,c) sum / sumsq ----------------
__global__ void __launch_bounds__(256) k_stats(const float* __restrict__ x) {
    int bc = blockIdx.x;
    int t  = threadIdx.x;
    const float* p = x + (size_t)bc * NN;
    float s = 0.f, sq = 0.f;
    #pragma unroll
    for (int i = 0; i < NN/256; i++) {
        float v = p[t + i*256];
        s += v;
        sq = fmaf(v, v, sq);
    }
    #pragma unroll
    for (int o = 16; o; o >>= 1) {
        s  += __shfl_down_sync(0xffffffffu, s,  o);
        sq += __shfl_down_sync(0xffffffffu, sq, o);
    }
    __shared__ float ss[8], sqs[8];
    if ((t & 31) == 0) { ss[t>>5] = s; sqs[t>>5] = sq; }
    __syncthreads();
    if (t == 0) {
        float a = 0.f, b2 = 0.f;
        #pragma unroll
        for (int w = 0; w < 8; w++) { a += ss[w]; b2 += sqs[w]; }
        g_chansum[bc] = a;
        g_chansq [bc] = b2;
    }
}

// ---------------- K1: group stats, weight folding, gate MLP ----------------
__global__ void __launch_bounds__(256) k_prep(
    const float* __restrict__ norm_w, const float* __restrict__ norm_b,
    const float* __restrict__ Wk, const float* __restrict__ Wv, const float* __restrict__ Wq,
    const float* __restrict__ Wg1, const float* __restrict__ bg1,
    const float* __restrict__ Wg2, const float* __restrict__ bg2,
    float* __restrict__ out, int has_tail, long long tail_off)
{
    int b = blockIdx.x;
    int t = threadIdx.x;
    __shared__ float mu_s[GG], rs_s[GG];
    __shared__ float alpha_s[Cc], beta_s[Cc], pooled[Cc];
    __shared__ float g1v[MDm];

    if (t < GG) {
        float s = 0.f, sq = 0.f;
        for (int c = 0; c < 32; c++) {
            s  += g_chansum[b*Cc + t*32 + c];
            sq += g_chansq [b*Cc + t*32 + c];
        }
        float inv = 1.0f / (32.0f * (float)NN);
        float mu  = s * inv;
        float var = sq * inv - mu * mu;
        mu_s[t] = mu;
        rs_s[t] = rsqrtf(var + 1e-5f);
    }
    __syncthreads();
    {
        int c = t, g = c >> 5;
        float a  = rs_s[g] * norm_w[c];
        float be = norm_b[c] - mu_s[g] * a;
        alpha_s[c] = a;
        beta_s [c] = be;
        pooled [c] = g_chansum[b*Cc + c] * (1.0f/(float)NN) * a + be;
    }
    __syncthreads();
    // fold alpha into stacked weights: W'[m][c] = W[m][c]*alpha[c]
    for (int m = 0; m < MKQV; m++) {
        const float* Wsrc = (m < 64) ? (Wk + m*Cc)
                          : (m < 128) ? (Wv + (m-64)*Cc)
                                      : (Wq + (m-128)*Cc);
        g_Wfold[(size_t)b*MKQV*Cc + m*Cc + t] = Wsrc[t] * alpha_s[t];
    }
    // pbias[m] = sum_c W[m][c]*beta[c]
    if (t < MKQV) {
        const float* Wsrc = (t < 64) ? (Wk + t*Cc)
                          : (t < 128) ? (Wv + (t-64)*Cc)
                                      : (Wq + (t-128)*Cc);
        float s = 0.f;
        for (int c = 0; c < Cc; c++) s = fmaf(Wsrc[c], beta_s[c], s);
        g_pbias[b*MKQV + t] = s;
    }
    __syncthreads();
    if (t < MDm) {
        float h = bg1[t];
        for (int c = 0; c < Cc; c++) h = fmaf(Wg1[t*Cc + c], pooled[c], h);
        g1v[t] = 0.5f * h * (1.0f + erff(h * 0.70710678118654752f)); // exact GELU
    }
    __syncthreads();
    if (t == 0) {
        float s = bg2[0];
        #pragma unroll
        for (int j = 0; j < MDm; j++) s = fmaf(Wg2[j], g1v[j], s);
        float gv = 1.0f / (1.0f + expf(-s));
        g_gate[b] = gv;
        if (has_tail) out[tail_off + b] = gv;
    }
}

// ---------------- K2: fused norm + KQV projection GEMM + phi epilogue ----------------
// BM=192(all outputs), BN=64, BK=16; 16x16 threads; 12x4 microtile
__global__ void __launch_bounds__(256) k_proj(const float* __restrict__ x) {
    int b  = blockIdx.y;
    int n0 = blockIdx.x * 64;
    int tx = threadIdx.x, ty = threadIdx.y;
    int tid = ty * 16 + tx;

    __shared__ float Wsh[16][MKQV];
    __shared__ float Xsh[16][68];

    float acc[12][4];
    #pragma unroll
    for (int i = 0; i < 12; i++)
        #pragma unroll
        for (int j = 0; j < 4; j++) acc[i][j] = 0.f;

    const float* xb = x + (size_t)b*Cc*NN + n0;
    const float* wb = g_Wfold + (size_t)b*MKQV*Cc;

    for (int kk = 0; kk < Cc; kk += 16) {
        #pragma unroll
        for (int i = 0; i < 12; i++) {
            int l = tid + i*256;
            int k = l & 15, m = l >> 4;
            Wsh[k][m] = wb[m*Cc + kk + k];
        }
        #pragma unroll
        for (int i = 0; i < 4; i++) {
            int l = tid + i*256;
            int n = l & 63, k = l >> 6;
            Xsh[k][n] = xb[(size_t)(kk + k)*NN + n];
        }
        __syncthreads();
        #pragma unroll
        for (int k = 0; k < 16; k++) {
            float wr[12], xr[4];
            #pragma unroll
            for (int i = 0; i < 12; i++) wr[i] = Wsh[k][ty + 16*i];
            #pragma unroll
            for (int j = 0; j < 4; j++)  xr[j] = Xsh[k][tx + 16*j];
            #pragma unroll
            for (int i = 0; i < 12; i++)
                #pragma unroll
                for (int j = 0; j < 4; j++)
                    acc[i][j] = fmaf(wr[i], xr[j], acc[i][j]);
        }
        __syncthreads();
    }

    #pragma unroll
    for (int i = 0; i < 12; i++) {
        int m = ty + 16*i;
        float pb = g_pbias[b*MKQV + m];
        bool isphi = (m < 64) || (m >= 128);   // k and q rows get elu+1
        #pragma unroll
        for (int j = 0; j < 4; j++) {
            float v = acc[i][j] + pb;
            if (isphi) v = (v > 0.f) ? (v + 1.f) : expf(v);
            g_kqv[((size_t)b*MKQV + m)*NN + n0 + tx + 16*j] = v;
        }
    }
}

// ---------------- K3: M = phi_k @ v^T + M0, Z = sum(phi_k) + Z0 per (b,h) ----------------
__global__ void __launch_bounds__(256) k_mz(const float* __restrict__ M0,
                                            const float* __restrict__ Z0) {
    int bh = blockIdx.x;
    int b = bh >> 2, h = bh & 3;
    int t = threadIdx.x;
    int d = t >> 4, e = t & 15;

    __shared__ __align__(16) float ph[16][260];
    __shared__ __align__(16) float vv[16][260];

    const float* kp = g_kqv + ((size_t)b*MKQV + h*HDd) * NN;
    const float* vp = kp + (size_t)64 * NN;

    float macc = 0.f, zacc = 0.f;
    for (int t0 = 0; t0 < NN; t0 += 256) {
        #pragma unroll
        for (int i = 0; i < 16; i++) {
            int l = t + i*256;
            int r = l >> 8, cidx = l & 255;
            ph[r][cidx] = kp[(size_t)r*NN + t0 + cidx];
            vv[r][cidx] = vp[(size_t)r*NN + t0 + cidx];
        }
        __syncthreads();
        #pragma unroll 8
        for (int u = 0; u < 256; u += 4) {
            float4 a  = *(const float4*)&ph[d][u];
            float4 bv = *(const float4*)&vv[e][u];
            macc = fmaf(a.x, bv.x, macc);
            macc = fmaf(a.y, bv.y, macc);
            macc = fmaf(a.z, bv.z, macc);
            macc = fmaf(a.w, bv.w, macc);
            if (e == 0) zacc += (a.x + a.y) + (a.z + a.w);
        }
        __syncthreads();
    }
    g_M[(bh*HDd + d)*HDd + e] = macc + M0[(h*HDd + d)*HDd + e];
    if (e == 0) g_Z[bh*HDd + d] = zacc + Z0[h*HDd + d];
}

// ---------------- K4: retrieval + Wout GEMM + residual/gate ----------------
__global__ void __launch_bounds__(256) k_out(const float* __restrict__ x,
                                             const float* __restrict__ Wout,
                                             const float* __restrict__ bout,
                                             float* __restrict__ out) {
    int b  = blockIdx.y;
    int n0 = blockIdx.x * 64;
    int t  = threadIdx.x;

    __shared__ __align__(16) float q  [64][68];
    __shared__ __align__(16) float ysh[64][68];
    __shared__ __align__(16) float Ms [NHh][HDd][HDd];
    __shared__ float Zs[64];
    __shared__ float rd[NHh][64];

    #pragma unroll
    for (int i = 0; i < 4; i++) {
        int idx = t + i*256;
        ((float*)Ms)[idx] = g_M[b*1024 + idx];
    }
    if (t < 64) Zs[t] = g_Z[b*64 + t];
    #pragma unroll
    for (int i = 0; i < 16; i++) {
        int l = t + i*256;
        int n = l & 63, m = l >> 6;
        q[m][n] = g_kqv[((size_t)b*MKQV + 128 + m)*NN + n0 + n];
    }
    __syncthreads();
    {   // denominator, clipped
        int h = t >> 6, n = t & 63;
        float s = 0.f;
        #pragma unroll
        for (int d2 = 0; d2 < 16; d2++)
            s = fmaf(Zs[h*16 + d2], q[h*16 + d2][n], s);
        rd[h][n] = 1.0f / fmaxf(s, 1e-4f);
    }
    __syncthreads();
    {   // y[m][n] = (sum_d M[h][d][e]*phi_q[d][n]) / den
        int n = t & 63, h = t >> 6;
        float qd[16];
        #pragma unroll
        for (int d2 = 0; d2 < 16; d2++) qd[d2] = q[h*16 + d2][n];
        float acc[16];
        #pragma unroll
        for (int j = 0; j < 16; j++) acc[j] = 0.f;
        #pragma unroll
        for (int d2 = 0; d2 < 16; d2++) {
            float qv = qd[d2];
            #pragma unroll
            for (int j = 0; j < 16; j++)
                acc[j] = fmaf(Ms[h][d2][j], qv, acc[j]);
        }
        float r = rd[h][n];
        #pragma unroll
        for (int j = 0; j < 16; j++) ysh[h*16 + j][n] = acc[j] * r;
    }
    __syncthreads();

    // out[c][n] = x + gate*(Wout[c,:]@y[:,n] + bout[c]); thread = c
    int c = t;
    float w[64];
    #pragma unroll
    for (int i4 = 0; i4 < 16; i4++) {
        float4 wv = *(const float4*)&Wout[c*64 + i4*4];
        w[i4*4+0] = wv.x; w[i4*4+1] = wv.y; w[i4*4+2] = wv.z; w[i4*4+3] = wv.w;
    }
    float gv = g_gate[b];
    float bo = bout[c];
    const float* xp = x   + ((size_t)b*Cc + c)*NN + n0;
    float*       op = out + ((size_t)b*Cc + c)*NN + n0;

    #pragma unroll
    for (int half = 0; half < 2; half++) {
        float acc[32];
        #pragma unroll
        for (int n = 0; n < 32; n++) acc[n] = 0.f;
        #pragma unroll 4
        for (int m = 0; m < 64; m++) {
            float wm = w[m];
            #pragma unroll
            for (int n4 = 0; n4 < 8; n4++) {
                float4 yv = *(const float4*)&ysh[m][half*32 + n4*4];
                acc[n4*4+0] = fmaf(wm, yv.x, acc[n4*4+0]);
                acc[n4*4+1] = fmaf(wm, yv.y, acc[n4*4+1]);
                acc[n4*4+2] = fmaf(wm, yv.z, acc[n4*4+2]);
                acc[n4*4+3] = fmaf(wm, yv.w, acc[n4*4+3]);
            }
        }
        #pragma unroll
        for (int n4 = 0; n4 < 8; n4++) {
            float4 xv = *(const float4*)&xp[half*32 + n4*4];
            float4 r;
            r.x = xv.x + gv * (acc[n4*4+0] + bo);
            r.y = xv.y + gv * (acc[n4*4+1] + bo);
            r.z = xv.z + gv * (acc[n4*4+2] + bo);
            r.w = xv.w + gv * (acc[n4*4+3] + bo);
            *(float4*)&op[half*32 + n4*4] = r;
        }
    }
}

// ---------------- launch ----------------
extern "C" void kernel_launch(void* const* d_in, const int* in_sizes, int n_in,
                              void* d_out, int out_size) {
    const float* x      = (const float*)d_in[0];
    const float* norm_w = (const float*)d_in[1];
    const float* norm_b = (const float*)d_in[2];
    const float* Wk     = (const float*)d_in[3];
    const float* Wv     = (const float*)d_in[4];
    const float* Wq     = (const float*)d_in[5];
    const float* Wout   = (const float*)d_in[6];
    const float* bout   = (const float*)d_in[7];
    const float* M0     = (const float*)d_in[8];
    const float* Z0     = (const float*)d_in[9];
    const float* Wg1    = (const float*)d_in[10];
    const float* bg1    = (const float*)d_in[11];
    const float* Wg2    = (const float*)d_in[12];
    const float* bg2    = (const float*)d_in[13];
    float* out = (float*)d_out;

    long long mainsz = (long long)Bb * Cc * NN;
    int has_tail = ((long long)out_size >= mainsz + Bb) ? 1 : 0;

    k_stats<<<Bb*Cc, 256>>>(x);
    k_prep <<<Bb, 256>>>(norm_w, norm_b, Wk, Wv, Wq, Wg1, bg1, Wg2, bg2,
                         out, has_tail, mainsz);
    k_proj <<<dim3(NN/64, Bb), dim3(16,16)>>>(x);
    k_mz   <<<Bb*NHh, 256>>>(M0, Z0);
    k_out  <<<dim3(NN/64, Bb), 256>>>(x, Wout, bout, out);
}

// round 2
// speedup vs baseline: 1.3972x; 1.3972x over previous
#include <cuda_runtime.h>
#include <math.h>

#define Bb   16
#define Cc   256
#define NN   9216      // H*W
#define GG   8
#define MDm  64
#define NHh  4
#define HDd  16
#define MKQV 192       // stacked k,v,q output rows
#define NBLK 144       // NN/64 column blocks

// ---------------- scratch (device globals: no allocs allowed) ----------------
__device__ float g_chansum[Bb*Cc];
__device__ float g_chansq [Bb*Cc];
__device__ float g_Wfold  [Bb*MKQV*Cc];          // per-batch alpha-folded stacked weights
__device__ float g_pbias  [Bb*MKQV];             // per-(b,o) beta-projection bias
__device__ float g_gate   [Bb];
__device__ float g_q      [(size_t)Bb*MDm*NN];   // phi_q only
__device__ float g_Mpart  [(size_t)Bb*NBLK*1024];
__device__ float g_Zpart  [(size_t)Bb*NBLK*64];
__device__ float g_M      [Bb*NHh*HDd*HDd];
__device__ float g_Z      [Bb*NHh*HDd];

// ---------------- K0: per-(b,c) sum / sumsq ----------------
__global__ void __launch_bounds__(256) k_stats(const float* __restrict__ x) {
    int bc = blockIdx.x;
    int t  = threadIdx.x;
    const float4* p = (const float4*)(x + (size_t)bc * NN);
    float s = 0.f, sq = 0.f;
    #pragma unroll
    for (int i = 0; i < NN/1024; i++) {
        float4 v = p[t + i*256];
        s += (v.x + v.y) + (v.z + v.w);
        sq = fmaf(v.x, v.x, sq);
        sq = fmaf(v.y, v.y, sq);
        sq = fmaf(v.z, v.z, sq);
        sq = fmaf(v.w, v.w, sq);
    }
    #pragma unroll
    for (int o = 16; o; o >>= 1) {
        s  += __shfl_down_sync(0xffffffffu, s,  o);
        sq += __shfl_down_sync(0xffffffffu, sq, o);
    }
    __shared__ float ss[8], sqs[8];
    if ((t & 31) == 0) { ss[t>>5] = s; sqs[t>>5] = sq; }
    __syncthreads();
    if (t == 0) {
        float a = 0.f, b2 = 0.f;
        #pragma unroll
        for (int w = 0; w < 8; w++) { a += ss[w]; b2 += sqs[w]; }
        g_chansum[bc] = a;
        g_chansq [bc] = b2;
    }
}

// ---------------- K1: group stats, weight folding, gate MLP ----------------
__global__ void __launch_bounds__(256) k_prep(
    const float* __restrict__ norm_w, const float* __restrict__ norm_b,
    const float* __restrict__ Wk, const float* __restrict__ Wv, const float* __restrict__ Wq,
    const float* __restrict__ Wg1, const float* __restrict__ bg1,
    const float* __restrict__ Wg2, const float* __restrict__ bg2,
    float* __restrict__ out, int has_tail, long long tail_off)
{
    int b = blockIdx.x;
    int t = threadIdx.x;
    __shared__ float mu_s[GG], rs_s[GG];
    __shared__ float alpha_s[Cc], beta_s[Cc], pooled[Cc];
    __shared__ float g1v[MDm];

    if (t < GG) {
        float s = 0.f, sq = 0.f;
        for (int c = 0; c < 32; c++) {
            s  += g_chansum[b*Cc + t*32 + c];
            sq += g_chansq [b*Cc + t*32 + c];
        }
        float inv = 1.0f / (32.0f * (float)NN);
        float mu  = s * inv;
        float var = sq * inv - mu * mu;
        mu_s[t] = mu;
        rs_s[t] = rsqrtf(var + 1e-5f);
    }
    __syncthreads();
    {
        int c = t, g = c >> 5;
        float a  = rs_s[g] * norm_w[c];
        float be = norm_b[c] - mu_s[g] * a;
        alpha_s[c] = a;
        beta_s [c] = be;
        pooled [c] = g_chansum[b*Cc + c] * (1.0f/(float)NN) * a + be;
    }
    __syncthreads();
    // fold alpha into stacked weights: W'[m][c] = W[m][c]*alpha[c]
    for (int m = 0; m < MKQV; m++) {
        const float* Wsrc = (m < 64) ? (Wk + m*Cc)
                          : (m < 128) ? (Wv + (m-64)*Cc)
                                      : (Wq + (m-128)*Cc);
        g_Wfold[(size_t)b*MKQV*Cc + m*Cc + t] = Wsrc[t] * alpha_s[t];
    }
    // pbias[m] = sum_c W[m][c]*beta[c]
    if (t < MKQV) {
        const float* Wsrc = (t < 64) ? (Wk + t*Cc)
                          : (t < 128) ? (Wv + (t-64)*Cc)
                                      : (Wq + (t-128)*Cc);
        float s = 0.f;
        for (int c = 0; c < Cc; c++) s = fmaf(Wsrc[c], beta_s[c], s);
        g_pbias[b*MKQV + t] = s;
    }
    __syncthreads();
    if (t < MDm) {
        float h = bg1[t];
        for (int c = 0; c < Cc; c++) h = fmaf(Wg1[t*Cc + c], pooled[c], h);
        g1v[t] = 0.5f * h * (1.0f + erff(h * 0.70710678118654752f)); // exact GELU
    }
    __syncthreads();
    if (t == 0) {
        float s = bg2[0];
        #pragma unroll
        for (int j = 0; j < MDm; j++) s = fmaf(Wg2[j], g1v[j], s);
        float gv = 1.0f / (1.0f + expf(-s));
        g_gate[b] = gv;
        if (has_tail) out[tail_off + b] = gv;
    }
}

// ---------------- K2: fused norm + KQV GEMM + phi + M/Z partial accumulation ----
// BM=192(all outputs), BN=64, BK=16; 256 threads; 12x4 microtile (vectorized)
__global__ void __launch_bounds__(256,2) k_proj(const float* __restrict__ x) {
    int b   = blockIdx.y;
    int nb  = blockIdx.x;
    int n0  = nb * 64;
    int tid = threadIdx.x;
    int tx  = tid & 15, ty = tid >> 4;

    __shared__ float Wsh[16][196];            // padded: conflict-free
    __shared__ float Xsh[16][64];
    __shared__ float KV [128][68];            // phi_k rows 0..63, v rows 64..127

    float acc[12][4];
    #pragma unroll
    for (int i = 0; i < 12; i++)
        #pragma unroll
        for (int j = 0; j < 4; j++) acc[i][j] = 0.f;

    const float* xb = x + (size_t)b*Cc*NN + n0;
    const float* wb = g_Wfold + (size_t)b*MKQV*Cc;

    for (int kk = 0; kk < Cc; kk += 16) {
        #pragma unroll
        for (int i = 0; i < 3; i++) {
            int l = tid + i*256;              // 0..767
            int m = l >> 2, kq = l & 3;
            float4 w4 = *(const float4*)(wb + m*Cc + kk + kq*4);
            Wsh[kq*4+0][m] = w4.x;
            Wsh[kq*4+1][m] = w4.y;
            Wsh[kq*4+2][m] = w4.z;
            Wsh[kq*4+3][m] = w4.w;
        }
        {
            int k = tid >> 4, n4 = tid & 15;
            float4 x4 = *(const float4*)(xb + (size_t)(kk + k)*NN + n4*4);
            *(float4*)&Xsh[k][n4*4] = x4;
        }
        __syncthreads();
        #pragma unroll
        for (int k = 0; k < 16; k++) {
            float4 xr = *(const float4*)&Xsh[k][tx*4];
            float4 w0 = *(const float4*)&Wsh[k][ty*12];
            float4 w1 = *(const float4*)&Wsh[k][ty*12 + 4];
            float4 w2 = *(const float4*)&Wsh[k][ty*12 + 8];
            float wv[12] = {w0.x,w0.y,w0.z,w0.w, w1.x,w1.y,w1.z,w1.w, w2.x,w2.y,w2.z,w2.w};
            float xf[4]  = {xr.x,xr.y,xr.z,xr.w};
            #pragma unroll
            for (int i = 0; i < 12; i++)
                #pragma unroll
                for (int j = 0; j < 4; j++)
                    acc[i][j] = fmaf(wv[i], xf[j], acc[i][j]);
        }
        __syncthreads();
    }

    // epilogue: phi_k/v -> KV smem, phi_q -> global
    float* qout = g_q + (size_t)b*MDm*NN + n0;
    #pragma unroll
    for (int i = 0; i < 12; i++) {
        int m = ty*12 + i;
        float pb = g_pbias[b*MKQV + m];
        float v0 = acc[i][0] + pb, v1 = acc[i][1] + pb;
        float v2 = acc[i][2] + pb, v3 = acc[i][3] + pb;
        if (m < 64 || m >= 128) {             // elu + 1
            v0 = (v0 > 0.f) ? (v0 + 1.f) : expf(v0);
            v1 = (v1 > 0.f) ? (v1 + 1.f) : expf(v1);
            v2 = (v2 > 0.f) ? (v2 + 1.f) : expf(v2);
            v3 = (v3 > 0.f) ? (v3 + 1.f) : expf(v3);
        }
        float4 r = make_float4(v0, v1, v2, v3);
        if (m < 128) {
            *(float4*)&KV[m][tx*4] = r;
        } else {
            *(float4*)(qout + (size_t)(m - 128)*NN + tx*4) = r;
        }
    }
    __syncthreads();

    // M partial: M[h][d][e] = sum_n phi_k[h*16+d][n] * v[h*16+e][n]
    {
        int h = tid >> 6, d = (tid >> 2) & 15, e0 = (tid & 3) * 4;
        float m0 = 0.f, m1 = 0.f, m2 = 0.f, m3 = 0.f;
        #pragma unroll
        for (int n = 0; n < 64; n += 4) {
            float4 a  = *(const float4*)&KV[h*16 + d][n];
            float4 b0 = *(const float4*)&KV[64 + h*16 + e0 + 0][n];
            float4 b1 = *(const float4*)&KV[64 + h*16 + e0 + 1][n];
            float4 b2 = *(const float4*)&KV[64 + h*16 + e0 + 2][n];
            float4 b3 = *(const float4*)&KV[64 + h*16 + e0 + 3][n];
            m0 = fmaf(a.x,b0.x, fmaf(a.y,b0.y, fmaf(a.z,b0.z, fmaf(a.w,b0.w, m0))));
            m1 = fmaf(a.x,b1.x, fmaf(a.y,b1.y, fmaf(a.z,b1.z, fmaf(a.w,b1.w, m1))));
            m2 = fmaf(a.x,b2.x, fmaf(a.y,b2.y, fmaf(a.z,b2.z, fmaf(a.w,b2.w, m2))));
            m3 = fmaf(a.x,b3.x, fmaf(a.y,b3.y, fmaf(a.z,b3.z, fmaf(a.w,b3.w, m3))));
        }
        // idx = h*256 + d*16 + e0 + j == tid*4 + j
        *(float4*)&g_Mpart[((size_t)(b*NBLK + nb))*1024 + tid*4] = make_float4(m0,m1,m2,m3);
    }
    if (tid < 64) {                           // Z partial: row sums of phi_k
        float z = 0.f;
        #pragma unroll
        for (int n = 0; n < 64; n += 4) {
            float4 a = *(const float4*)&KV[tid][n];
            z += (a.x + a.y) + (a.z + a.w);
        }
        g_Zpart[((size_t)(b*NBLK + nb))*64 + tid] = z;
    }
}

// ---------------- K3: reduce partials -> M, Z ----------------
__global__ void __launch_bounds__(256) k_red(const float* __restrict__ M0,
                                             const float* __restrict__ Z0) {
    int b = blockIdx.x;
    int t = threadIdx.x;
    float4 s = make_float4(0.f,0.f,0.f,0.f);
    const float* base = g_Mpart + (size_t)b*NBLK*1024;
    for (int nb = 0; nb < NBLK; nb++) {
        float4 p = *(const float4*)(base + (size_t)nb*1024 + t*4);
        s.x += p.x; s.y += p.y; s.z += p.z; s.w += p.w;
    }
    float4 m0v = *(const float4*)&M0[t*4];
    s.x += m0v.x; s.y += m0v.y; s.z += m0v.z; s.w += m0v.w;
    *(float4*)&g_M[b*1024 + t*4] = s;
    if (t < 64) {
        float z = 0.f;
        const float* zb = g_Zpart + (size_t)b*NBLK*64;
        for (int nb = 0; nb < NBLK; nb++) z += zb[nb*64 + t];
        g_Z[b*64 + t] = z + Z0[t];
    }
}

// ---------------- K4: retrieval + Wout GEMM + residual/gate ----------------
__global__ void __launch_bounds__(256) k_out(const float* __restrict__ x,
                                             const float* __restrict__ Wout,
                                             const float* __restrict__ bout,
                                             float* __restrict__ out) {
    int b  = blockIdx.y;
    int n0 = blockIdx.x * 64;
    int t  = threadIdx.x;

    __shared__ __align__(16) float q  [64][68];
    __shared__ __align__(16) float ysh[64][68];
    __shared__ __align__(16) float Ms [NHh][HDd][HDd];
    __shared__ float Zs[64];
    __shared__ float rd[NHh][64];

    #pragma unroll
    for (int i = 0; i < 4; i++) {
        int idx = t + i*256;
        ((float*)Ms)[idx] = g_M[b*1024 + idx];
    }
    if (t < 64) Zs[t] = g_Z[b*64 + t];
    #pragma unroll
    for (int i = 0; i < 16; i++) {
        int l = t + i*256;
        int n = l & 63, m = l >> 6;
        q[m][n] = g_q[((size_t)b*MDm + m)*NN + n0 + n];
    }
    __syncthreads();
    {   // denominator, clipped
        int h = t >> 6, n = t & 63;
        float s = 0.f;
        #pragma unroll
        for (int d2 = 0; d2 < 16; d2++)
            s = fmaf(Zs[h*16 + d2], q[h*16 + d2][n], s);
        rd[h][n] = 1.0f / fmaxf(s, 1e-4f);
    }
    __syncthreads();
    {   // y[m][n] = (sum_d M[h][d][e]*phi_q[d][n]) / den
        int n = t & 63, h = t >> 6;
        float qd[16];
        #pragma unroll
        for (int d2 = 0; d2 < 16; d2++) qd[d2] = q[h*16 + d2][n];
        float acc[16];
        #pragma unroll
        for (int j = 0; j < 16; j++) acc[j] = 0.f;
        #pragma unroll
        for (int d2 = 0; d2 < 16; d2++) {
            float qv = qd[d2];
            #pragma unroll
            for (int j = 0; j < 16; j++)
                acc[j] = fmaf(Ms[h][d2][j], qv, acc[j]);
        }
        float r = rd[h][n];
        #pragma unroll
        for (int j = 0; j < 16; j++) ysh[h*16 + j][n] = acc[j] * r;
    }
    __syncthreads();

    // out[c][n] = x + gate*(Wout[c,:]@y[:,n] + bout[c]); thread = c
    int c = t;
    float w[64];
    #pragma unroll
    for (int i4 = 0; i4 < 16; i4++) {
        float4 wv = *(const float4*)&Wout[c*64 + i4*4];
        w[i4*4+0] = wv.x; w[i4*4+1] = wv.y; w[i4*4+2] = wv.z; w[i4*4+3] = wv.w;
    }
    float gv = g_gate[b];
    float bo = bout[c];
    const float* xp = x   + ((size_t)b*Cc + c)*NN + n0;
    float*       op = out + ((size_t)b*Cc + c)*NN + n0;

    #pragma unroll
    for (int half = 0; half < 2; half++) {
        float acc[32];
        #pragma unroll
        for (int n = 0; n < 32; n++) acc[n] = 0.f;
        #pragma unroll 4
        for (int m = 0; m < 64; m++) {
            float wm = w[m];
            #pragma unroll
            for (int n4 = 0; n4 < 8; n4++) {
                float4 yv = *(const float4*)&ysh[m][half*32 + n4*4];
                acc[n4*4+0] = fmaf(wm, yv.x, acc[n4*4+0]);
                acc[n4*4+1] = fmaf(wm, yv.y, acc[n4*4+1]);
                acc[n4*4+2] = fmaf(wm, yv.z, acc[n4*4+2]);
                acc[n4*4+3] = fmaf(wm, yv.w, acc[n4*4+3]);
            }
        }
        #pragma unroll
        for (int n4 = 0; n4 < 8; n4++) {
            float4 xv = *(const float4*)&xp[half*32 + n4*4];
            float4 r;
            r.x = xv.x + gv * (acc[n4*4+0] + bo);
            r.y = xv.y + gv * (acc[n4*4+1] + bo);
            r.z = xv.z + gv * (acc[n4*4+2] + bo);
            r.w = xv.w + gv * (acc[n4*4+3] + bo);
            *(float4*)&op[half*32 + n4*4] = r;
        }
    }
}

// ---------------- launch ----------------
extern "C" void kernel_launch(void* const* d_in, const int* in_sizes, int n_in,
                              void* d_out, int out_size) {
    const float* x      = (const float*)d_in[0];
    const float* norm_w = (const float*)d_in[1];
    const float* norm_b = (const float*)d_in[2];
    const float* Wk     = (const float*)d_in[3];
    const float* Wv     = (const float*)d_in[4];
    const float* Wq     = (const float*)d_in[5];
    const float* Wout   = (const float*)d_in[6];
    const float* bout   = (const float*)d_in[7];
    const float* M0     = (const float*)d_in[8];
    const float* Z0     = (const float*)d_in[9];
    const float* Wg1    = (const float*)d_in[10];
    const float* bg1    = (const float*)d_in[11];
    const float* Wg2    = (const float*)d_in[12];
    const float* bg2    = (const float*)d_in[13];
    float* out = (float*)d_out;

    long long mainsz = (long long)Bb * Cc * NN;
    int has_tail = ((long long)out_size >= mainsz + Bb) ? 1 : 0;

    k_stats<<<Bb*Cc, 256>>>(x);
    k_prep <<<Bb, 256>>>(norm_w, norm_b, Wk, Wv, Wq, Wg1, bg1, Wg2, bg2,
                         out, has_tail, mainsz);
    k_proj <<<dim3(NBLK, Bb), 256>>>(x);
    k_red  <<<Bb, 256>>>(M0, Z0);
    k_out  <<<dim3(NBLK, Bb), 256>>>(x, Wout, bout, out);
}

// round 4
// speedup vs baseline: 1.7670x; 1.2646x over previous
#include <cuda_runtime.h>
#include <cuda_bf16.h>
#include <math.h>
#include <stdint.h>

#define Bb   16
#define Cc   256
#define NN   9216      // H*W
#define GG   8
#define MDm  64
#define NHh  4
#define HDd  16
#define MKQV 192
#define NBLK 144       // NN/64 column blocks

// ---------------- scratch (device globals: no allocs allowed) ----------------
__device__ float g_chansum[Bb*Cc];
__device__ float g_chansq [Bb*Cc];
__device__ __nv_bfloat16 g_Wh[(size_t)Bb*MKQV*Cc];
__device__ __nv_bfloat16 g_Wl[(size_t)Bb*MKQV*Cc];
__device__ float g_pbias  [Bb*MKQV];
__device__ float g_gate   [Bb];
__device__ float g_q      [(size_t)Bb*MDm*NN];   // phi_q only
__device__ float g_Mpart  [(size_t)Bb*NBLK*1024];
__device__ float g_Zpart  [(size_t)Bb*NBLK*64];
__device__ float g_M      [Bb*NHh*HDd*HDd];
__device__ float g_Z      [Bb*NHh*HDd];

// ---------------- PTX helpers (baseline ISA only: ldmatrix + mma.sync) -------
__device__ __forceinline__ uint32_t smem_u32(const void* p) {
    uint32_t a;
    asm("{ .reg .u64 t; cvta.to.shared.u64 t, %1; cvt.u32.u64 %0, t; }" : "=r"(a) : "l"(p));
    return a;
}
__device__ __forceinline__ void ldsm4(uint32_t* r, uint32_t addr) {
    asm volatile("ldmatrix.sync.aligned.m8n8.x4.shared.b16 {%0,%1,%2,%3}, [%4];"
        : "=r"(r[0]), "=r"(r[1]), "=r"(r[2]), "=r"(r[3]) : "r"(addr));
}
__device__ __forceinline__ void ldsm4t(uint32_t* r, uint32_t addr) {
    asm volatile("ldmatrix.sync.aligned.m8n8.x4.trans.shared.b16 {%0,%1,%2,%3}, [%4];"
        : "=r"(r[0]), "=r"(r[1]), "=r"(r[2]), "=r"(r[3]) : "r"(addr));
}
__device__ __forceinline__ void mma16816(float* d, const uint32_t* a, const uint32_t* b) {
    asm volatile("mma.sync.aligned.m16n8k16.row.col.f32.bf16.bf16.f32 "
        "{%0,%1,%2,%3}, {%4,%5,%6,%7}, {%8,%9}, {%0,%1,%2,%3};"
        : "+f"(d[0]), "+f"(d[1]), "+f"(d[2]), "+f"(d[3])
        : "r"(a[0]), "r"(a[1]), "r"(a[2]), "r"(a[3]), "r"(b[0]), "r"(b[1]));
}

// ---------------- K0: per-(b,c) sum / sumsq ----------------
__global__ void __launch_bounds__(256) k_stats(const float* __restrict__ x) {
    int bc = blockIdx.x;
    int t  = threadIdx.x;
    const float4* p = (const float4*)(x + (size_t)bc * NN);
    float s = 0.f, sq = 0.f;
    #pragma unroll
    for (int i = 0; i < NN/1024; i++) {
        float4 v = p[t + i*256];
        s += (v.x + v.y) + (v.z + v.w);
        sq = fmaf(v.x, v.x, sq);
        sq = fmaf(v.y, v.y, sq);
        sq = fmaf(v.z, v.z, sq);
        sq = fmaf(v.w, v.w, sq);
    }
    #pragma unroll
    for (int o = 16; o; o >>= 1) {
        s  += __shfl_down_sync(0xffffffffu, s,  o);
        sq += __shfl_down_sync(0xffffffffu, sq, o);
    }
    __shared__ float ss[8], sqs[8];
    if ((t & 31) == 0) { ss[t>>5] = s; sqs[t>>5] = sq; }
    __syncthreads();
    if (t == 0) {
        float a = 0.f, b2 = 0.f;
        #pragma unroll
        for (int w = 0; w < 8; w++) { a += ss[w]; b2 += sqs[w]; }
        g_chansum[bc] = a;
        g_chansq [bc] = b2;
    }
}

// ---------------- K1: group stats, weight fold+split, gate MLP ----------------
__global__ void __launch_bounds__(256) k_prep(
    const float* __restrict__ norm_w, const float* __restrict__ norm_b,
    const float* __restrict__ Wk, const float* __restrict__ Wv, const float* __restrict__ Wq,
    const float* __restrict__ Wg1, const float* __restrict__ bg1,
    const float* __restrict__ Wg2, const float* __restrict__ bg2,
    float* __restrict__ out, int has_tail, long long tail_off)
{
    int b = blockIdx.x;
    int t = threadIdx.x;
    __shared__ float mu_s[GG], rs_s[GG];
    __shared__ float alpha_s[Cc], beta_s[Cc], pooled[Cc];
    __shared__ float g1v[MDm];

    if (t < GG) {
        float s = 0.f, sq = 0.f;
        for (int c = 0; c < 32; c++) {
            s  += g_chansum[b*Cc + t*32 + c];
            sq += g_chansq [b*Cc + t*32 + c];
        }
        float inv = 1.0f / (32.0f * (float)NN);
        float mu  = s * inv;
        float var = sq * inv - mu * mu;
        mu_s[t] = mu;
        rs_s[t] = rsqrtf(var + 1e-5f);
    }
    __syncthreads();
    {
        int c = t, g = c >> 5;
        float a  = rs_s[g] * norm_w[c];
        float be = norm_b[c] - mu_s[g] * a;
        alpha_s[c] = a;
        beta_s [c] = be;
        pooled [c] = g_chansum[b*Cc + c] * (1.0f/(float)NN) * a + be;
    }
    __syncthreads();
    // fold alpha into stacked weights, split into bf16 hi/lo
    for (int m = 0; m < MKQV; m++) {
        const float* Wsrc = (m < 64) ? (Wk + m*Cc)
                          : (m < 128) ? (Wv + (m-64)*Cc)
                                      : (Wq + (m-128)*Cc);
        float wf = Wsrc[t] * alpha_s[t];
        __nv_bfloat16 h = __float2bfloat16_rn(wf);
        g_Wh[(size_t)b*MKQV*Cc + m*Cc + t] = h;
        g_Wl[(size_t)b*MKQV*Cc + m*Cc + t] = __float2bfloat16_rn(wf - __bfloat162float(h));
    }
    if (t < MKQV) {
        const float* Wsrc = (t < 64) ? (Wk + t*Cc)
                          : (t < 128) ? (Wv + (t-64)*Cc)
                                      : (Wq + (t-128)*Cc);
        float s = 0.f;
        for (int c = 0; c < Cc; c++) s = fmaf(Wsrc[c], beta_s[c], s);
        g_pbias[b*MKQV + t] = s;
    }
    __syncthreads();
    if (t < MDm) {
        float h = bg1[t];
        for (int c = 0; c < Cc; c++) h = fmaf(Wg1[t*Cc + c], pooled[c], h);
        g1v[t] = 0.5f * h * (1.0f + erff(h * 0.70710678118654752f));
    }
    __syncthreads();
    if (t == 0) {
        float s = bg2[0];
        #pragma unroll
        for (int j = 0; j < MDm; j++) s = fmaf(Wg2[j], g1v[j], s);
        float gv = 1.0f / (1.0f + expf(-s));
        g_gate[b] = gv;
        if (has_tail) out[tail_off + b] = gv;
    }
}

// ---------------- K2: HMMA KQV GEMM (bf16 hi/lo split) + phi + M/Z partials --
// smem layout (dynamic). A rows padded to 72 bf16 (144B) for conflict-free ldmatrix.
#define S_AH    0                         // bf16 A hi: 192 x 72   (27648 B)
#define S_AL    27648                     // bf16 A lo             (27648 B)
#define S_BH    55296                     // bf16 B hi: 64 x 72    ( 9216 B)
#define S_BL    64512                     // bf16 B lo             ( 9216 B)
#define S_TOTAL 73728
// epilogue union (after all MMAs done):
#define S_KV    0                         // float[128][68]  (34816 B)
#define S_QS    36864                     // float[64][68]   (17408 B)

__global__ void __launch_bounds__(256) k_proj(const float* __restrict__ x) {
    extern __shared__ char smem[];
    uint32_t sb = smem_u32(smem);
    int b   = blockIdx.y;
    int nb  = blockIdx.x;
    int n0  = nb * 64;
    int tid = threadIdx.x;
    int wid = tid >> 5, lane = tid & 31;
    int warp_m = wid >> 1;                 // 0..3 -> M rows warp_m*48..+48
    int warp_n = wid & 1;                  // 0..1 -> N cols warp_n*32..+32

    const float* xb = x + (size_t)b*Cc*NN + n0;
    const __nv_bfloat16* wh = g_Wh + (size_t)b*MKQV*Cc;
    const __nv_bfloat16* wl = g_Wl + (size_t)b*MKQV*Cc;

    float acc[3][4][4];
    #pragma unroll
    for (int i = 0; i < 3; i++)
        #pragma unroll
        for (int j = 0; j < 4; j++)
            #pragma unroll
            for (int r = 0; r < 4; r++) acc[i][j][r] = 0.f;

    // per-thread ldmatrix base addresses
    uint32_t aRowOff  = (uint32_t)(warp_m*48 + (lane & 15)) * 144 + (lane >> 4) * 16;
    uint32_t bRowOff  = (uint32_t)(lane & 15) * 144
                      + (uint32_t)(warp_n*32 + (lane >> 4) * 8) * 2;

    for (int c = 0; c < 4; c++) {
        int kk = c * 64;
        __syncthreads();                   // prev chunk fully consumed
        // stage A hi/lo: 192 rows x 64 cols bf16 (uint4 = 8 bf16)
        #pragma unroll
        for (int i = 0; i < 6; i++) {
            int l = tid + i*256;
            int m = l >> 3, j = l & 7;
            *(uint4*)(smem + S_AH + m*144 + j*16) = *(const uint4*)(wh + (size_t)m*Cc + kk + j*8);
            *(uint4*)(smem + S_AL + m*144 + j*16) = *(const uint4*)(wl + (size_t)m*Cc + kk + j*8);
        }
        // stage B hi/lo with fp32->bf16 split: 64 k-rows x 64 n
        #pragma unroll
        for (int i = 0; i < 4; i++) {
            int l = tid + i*256;
            int k = l >> 4, n4 = l & 15;
            float4 v = *(const float4*)(xb + (size_t)(kk + k)*NN + n4*4);
            __nv_bfloat16 h0 = __float2bfloat16_rn(v.x);
            __nv_bfloat16 h1 = __float2bfloat16_rn(v.y);
            __nv_bfloat16 h2 = __float2bfloat16_rn(v.z);
            __nv_bfloat16 h3 = __float2bfloat16_rn(v.w);
            __nv_bfloat16 l0 = __float2bfloat16_rn(v.x - __bfloat162float(h0));
            __nv_bfloat16 l1 = __float2bfloat16_rn(v.y - __bfloat162float(h1));
            __nv_bfloat16 l2 = __float2bfloat16_rn(v.z - __bfloat162float(h2));
            __nv_bfloat16 l3 = __float2bfloat16_rn(v.w - __bfloat162float(h3));
            uint2 uh, ul;
            uh.x = ((uint32_t)__bfloat16_as_ushort(h1) << 16) | __bfloat16_as_ushort(h0);
            uh.y = ((uint32_t)__bfloat16_as_ushort(h3) << 16) | __bfloat16_as_ushort(h2);
            ul.x = ((uint32_t)__bfloat16_as_ushort(l1) << 16) | __bfloat16_as_ushort(l0);
            ul.y = ((uint32_t)__bfloat16_as_ushort(l3) << 16) | __bfloat16_as_ushort(l2);
            *(uint2*)(smem + S_BH + k*144 + n4*8) = uh;
            *(uint2*)(smem + S_BL + k*144 + n4*8) = ul;
        }
        __syncthreads();

        #pragma unroll
        for (int ks = 0; ks < 4; ks++) {
            uint32_t kByte = (uint32_t)(ks * 16) * 2;
            uint32_t ah[3][4], al[3][4], bh[2][4], bl[2][4];
            #pragma unroll
            for (int fm = 0; fm < 3; fm++) {
                uint32_t ao = aRowOff + (uint32_t)fm*16*144 + kByte;
                ldsm4(ah[fm], sb + S_AH + ao);
                ldsm4(al[fm], sb + S_AL + ao);
            }
            #pragma unroll
            for (int p = 0; p < 2; p++) {
                uint32_t bo = bRowOff + (uint32_t)(ks*16)*144 + (uint32_t)p*16*2;
                ldsm4t(bh[p], sb + S_BH + bo);
                ldsm4t(bl[p], sb + S_BL + bo);
            }
            #pragma unroll
            for (int fm = 0; fm < 3; fm++) {
                #pragma unroll
                for (int p = 0; p < 2; p++) {
                    // fragment for n = p*16 .. +7 is regs [0..1], n+8 is [2..3]
                    mma16816(acc[fm][p*2+0], ah[fm], &bh[p][0]);
                    mma16816(acc[fm][p*2+1], ah[fm], &bh[p][2]);
                    mma16816(acc[fm][p*2+0], ah[fm], &bl[p][0]);
                    mma16816(acc[fm][p*2+1], ah[fm], &bl[p][2]);
                    mma16816(acc[fm][p*2+0], al[fm], &bh[p][0]);
                    mma16816(acc[fm][p*2+1], al[fm], &bh[p][2]);
                }
            }
        }
    }
    __syncthreads();                       // operand smem dead; reuse for epilogue

    float (*KV)[68] = (float(*)[68])(smem + S_KV);
    float (*QS)[68] = (float(*)[68])(smem + S_QS);

    // scatter accumulators with pbias + phi
    #pragma unroll
    for (int fm = 0; fm < 3; fm++) {
        #pragma unroll
        for (int fn = 0; fn < 4; fn++) {
            float* d = acc[fm][fn];
            int n = warp_n*32 + fn*8 + (lane & 3)*2;
            #pragma unroll
            for (int rh = 0; rh < 2; rh++) {
                int m = warp_m*48 + fm*16 + (lane >> 2) + rh*8;
                float pb = g_pbias[b*MKQV + m];
                float v0 = d[rh*2+0] + pb, v1 = d[rh*2+1] + pb;
                if (m < 64 || m >= 128) {
                    v0 = (v0 > 0.f) ? (v0 + 1.f) : expf(v0);
                    v1 = (v1 > 0.f) ? (v1 + 1.f) : expf(v1);
                }
                float2 o = make_float2(v0, v1);
                if (m < 128) *(float2*)&KV[m][n]      = o;
                else         *(float2*)&QS[m-128][n]  = o;
            }
        }
    }
    __syncthreads();

    // q writeout (coalesced)
    {
        int r2 = tid >> 2, qt = tid & 3;
        float* dst = g_q + ((size_t)b*MDm + r2)*NN + n0 + qt*16;
        #pragma unroll
        for (int j = 0; j < 4; j++)
            *(float4*)(dst + j*4) = *(const float4*)&QS[r2][qt*16 + j*4];
    }
    // M partial: M[h][d][e] = sum_n phi_k[h*16+d][n] * v[h*16+e][n]
    {
        int h = tid >> 6, d = (tid >> 2) & 15, e0 = (tid & 3) * 4;
        float m0 = 0.f, m1 = 0.f, m2 = 0.f, m3 = 0.f;
        #pragma unroll
        for (int n = 0; n < 64; n += 4) {
            float4 a  = *(const float4*)&KV[h*16 + d][n];
            float4 b0 = *(const float4*)&KV[64 + h*16 + e0 + 0][n];
            float4 b1 = *(const float4*)&KV[64 + h*16 + e0 + 1][n];
            float4 b2 = *(const float4*)&KV[64 + h*16 + e0 + 2][n];
            float4 b3 = *(const float4*)&KV[64 + h*16 + e0 + 3][n];
            m0 = fmaf(a.x,b0.x, fmaf(a.y,b0.y, fmaf(a.z,b0.z, fmaf(a.w,b0.w, m0))));
            m1 = fmaf(a.x,b1.x, fmaf(a.y,b1.y, fmaf(a.z,b1.z, fmaf(a.w,b1.w, m1))));
            m2 = fmaf(a.x,b2.x, fmaf(a.y,b2.y, fmaf(a.z,b2.z, fmaf(a.w,b2.w, m2))));
            m3 = fmaf(a.x,b3.x, fmaf(a.y,b3.y, fmaf(a.z,b3.z, fmaf(a.w,b3.w, m3))));
        }
        *(float4*)&g_Mpart[((size_t)(b*NBLK + nb))*1024 + tid*4] = make_float4(m0,m1,m2,m3);
    }
    if (tid < 64) {
        float z = 0.f;
        #pragma unroll
        for (int n = 0; n < 64; n += 4) {
            float4 a = *(const float4*)&KV[tid][n];
            z += (a.x + a.y) + (a.z + a.w);
        }
        g_Zpart[((size_t)(b*NBLK + nb))*64 + tid] = z;
    }
}

// ---------------- K3: reduce partials -> M, Z (parallelized) ----------------
__global__ void __launch_bounds__(128) k_red(const float* __restrict__ M0,
                                             const float* __restrict__ Z0) {
    int b = blockIdx.y, s = blockIdx.x;
    int t = threadIdx.x;
    int idx = s*128 + t;
    float acc = 0.f;
    const float* base = g_Mpart + (size_t)b*NBLK*1024 + idx;
    #pragma unroll 4
    for (int nb = 0; nb < NBLK; nb++) acc += base[(size_t)nb*1024];
    g_M[b*1024 + idx] = acc + M0[idx];
    if (t < 8) {
        int z = s*8 + t;
        float za = 0.f;
        const float* zb = g_Zpart + (size_t)b*NBLK*64 + z;
        #pragma unroll 4
        for (int nb = 0; nb < NBLK; nb++) za += zb[nb*64];
        g_Z[b*64 + z] = za + Z0[z];
    }
}

// ---------------- K4: retrieval + Wout GEMM + residual/gate ----------------
__global__ void __launch_bounds__(256) k_out(const float* __restrict__ x,
                                             const float* __restrict__ Wout,
                                             const float* __restrict__ bout,
                                             float* __restrict__ out) {
    int b  = blockIdx.y;
    int n0 = blockIdx.x * 64;
    int t  = threadIdx.x;

    __shared__ __align__(16) float q  [64][68];
    __shared__ __align__(16) float ysh[64][68];
    __shared__ __align__(16) float Ms [NHh][HDd][HDd];
    __shared__ float Zs[64];
    __shared__ float rd[NHh][64];

    #pragma unroll
    for (int i = 0; i < 4; i++) {
        int idx = t + i*256;
        ((float*)Ms)[idx] = g_M[b*1024 + idx];
    }
    if (t < 64) Zs[t] = g_Z[b*64 + t];
    #pragma unroll
    for (int i = 0; i < 16; i++) {
        int l = t + i*256;
        int n = l & 63, m = l >> 6;
        q[m][n] = g_q[((size_t)b*MDm + m)*NN + n0 + n];
    }
    __syncthreads();
    {
        int h = t >> 6, n = t & 63;
        float s = 0.f;
        #pragma unroll
        for (int d2 = 0; d2 < 16; d2++)
            s = fmaf(Zs[h*16 + d2], q[h*16 + d2][n], s);
        rd[h][n] = 1.0f / fmaxf(s, 1e-4f);
    }
    __syncthreads();
    {
        int n = t & 63, h = t >> 6;
        float qd[16];
        #pragma unroll
        for (int d2 = 0; d2 < 16; d2++) qd[d2] = q[h*16 + d2][n];
        float acc[16];
        #pragma unroll
        for (int j = 0; j < 16; j++) acc[j] = 0.f;
        #pragma unroll
        for (int d2 = 0; d2 < 16; d2++) {
            float qv = qd[d2];
            #pragma unroll
            for (int j = 0; j < 16; j++)
                acc[j] = fmaf(Ms[h][d2][j], qv, acc[j]);
        }
        float r = rd[h][n];
        #pragma unroll
        for (int j = 0; j < 16; j++) ysh[h*16 + j][n] = acc[j] * r;
    }
    __syncthreads();

    int c = t;
    float w[64];
    #pragma unroll
    for (int i4 = 0; i4 < 16; i4++) {
        float4 wv = *(const float4*)&Wout[c*64 + i4*4];
        w[i4*4+0] = wv.x; w[i4*4+1] = wv.y; w[i4*4+2] = wv.z; w[i4*4+3] = wv.w;
    }
    float gv = g_gate[b];
    float bo = bout[c];
    const float* xp = x   + ((size_t)b*Cc + c)*NN + n0;
    float*       op = out + ((size_t)b*Cc + c)*NN + n0;

    #pragma unroll
    for (int half = 0; half < 2; half++) {
        float acc[32];
        #pragma unroll
        for (int n = 0; n < 32; n++) acc[n] = 0.f;
        #pragma unroll 4
        for (int m = 0; m < 64; m++) {
            float wm = w[m];
            #pragma unroll
            for (int n4 = 0; n4 < 8; n4++) {
                float4 yv = *(const float4*)&ysh[m][half*32 + n4*4];
                acc[n4*4+0] = fmaf(wm, yv.x, acc[n4*4+0]);
                acc[n4*4+1] = fmaf(wm, yv.y, acc[n4*4+1]);
                acc[n4*4+2] = fmaf(wm, yv.z, acc[n4*4+2]);
                acc[n4*4+3] = fmaf(wm, yv.w, acc[n4*4+3]);
            }
        }
        #pragma unroll
        for (int n4 = 0; n4 < 8; n4++) {
            float4 xv = *(const float4*)&xp[half*32 + n4*4];
            float4 r;
            r.x = xv.x + gv * (acc[n4*4+0] + bo);
            r.y = xv.y + gv * (acc[n4*4+1] + bo);
            r.z = xv.z + gv * (acc[n4*4+2] + bo);
            r.w = xv.w + gv * (acc[n4*4+3] + bo);
            *(float4*)&op[half*32 + n4*4] = r;
        }
    }
}

// ---------------- launch ----------------
extern "C" void kernel_launch(void* const* d_in, const int* in_sizes, int n_in,
                              void* d_out, int out_size) {
    const float* x      = (const float*)d_in[0];
    const float* norm_w = (const float*)d_in[1];
    const float* norm_b = (const float*)d_in[2];
    const float* Wk     = (const float*)d_in[3];
    const float* Wv     = (const float*)d_in[4];
    const float* Wq     = (const float*)d_in[5];
    const float* Wout   = (const float*)d_in[6];
    const float* bout   = (const float*)d_in[7];
    const float* M0     = (const float*)d_in[8];
    const float* Z0     = (const float*)d_in[9];
    const float* Wg1    = (const float*)d_in[10];
    const float* bg1    = (const float*)d_in[11];
    const float* Wg2    = (const float*)d_in[12];
    const float* bg2    = (const float*)d_in[13];
    float* out = (float*)d_out;

    long long mainsz = (long long)Bb * Cc * NN;
    int has_tail = ((long long)out_size >= mainsz + Bb) ? 1 : 0;

    cudaFuncSetAttribute(k_proj, cudaFuncAttributeMaxDynamicSharedMemorySize, S_TOTAL);

    k_stats<<<Bb*Cc, 256>>>(x);
    k_prep <<<Bb, 256>>>(norm_w, norm_b, Wk, Wv, Wq, Wg1, bg1, Wg2, bg2,
                         out, has_tail, mainsz);
    k_proj <<<dim3(NBLK, Bb), 256, S_TOTAL>>>(x);
    k_red  <<<dim3(8, Bb), 128>>>(M0, Z0);
    k_out  <<<dim3(NBLK, Bb), 256>>>(x, Wout, bout, out);
}